// round 15
// baseline (speedup 1.0000x reference)
#include <cuda_runtime.h>
#include <cuda_bf16.h>
#include <cstdint>

// Problem constants
#define HH 256
#define WW 256
#define BB 4
#define CC 64
#define KOFF 18
#define HWP (HH*WW)

// Scratch (device-global)
__device__ float g_feat[BB*CC*HH*WW];            // 64 MiB
__device__ float g_off [BB*KOFF*HH*WW];          // 18 MiB
// deform weights in per-lane HMMA fragment order
__device__ uint32_t g_wfragH[9*4*4*32*4];
__device__ uint32_t g_wfragL[9*4*4*32*4];
// offset-conv weights, frag order (N padded 18->32)
__device__ uint32_t g_ofragH[9*4*2*32*4];
__device__ uint32_t g_ofragL[9*4*2*32*4];

typedef unsigned long long u64;

// ---------------------------------------------------------------------------
// helpers
// ---------------------------------------------------------------------------
__device__ __forceinline__ uint32_t smem_u32(const void* p) {
    uint32_t a;
    asm("{ .reg .u64 t; cvta.to.shared.u64 t, %1; cvt.u32.u64 %0, t; }"
        : "=r"(a) : "l"(p));
    return a;
}
#define SWZ(b) ((b) ^ (((b) >> 3) & 0x70))

__device__ __forceinline__ void ldsm4(uint32_t* r, uint32_t addr) {
    asm volatile("ldmatrix.sync.aligned.m8n8.x4.shared.b16 {%0,%1,%2,%3}, [%4];"
        : "=r"(r[0]), "=r"(r[1]), "=r"(r[2]), "=r"(r[3]) : "r"(addr));
}
__device__ __forceinline__ void mma16816(float* d, const uint32_t* a, const uint32_t* b) {
    asm volatile(
        "mma.sync.aligned.m16n8k16.row.col.f32.bf16.bf16.f32 "
        "{%0,%1,%2,%3}, {%4,%5,%6,%7}, {%8,%9}, {%0,%1,%2,%3};"
        : "+f"(d[0]), "+f"(d[1]), "+f"(d[2]), "+f"(d[3])
        : "r"(a[0]), "r"(a[1]), "r"(a[2]), "r"(a[3]), "r"(b[0]), "r"(b[1]));
}

// split-bf16 pack helper: 2 floats -> (hi bf16x2, lo bf16x2)
__device__ __forceinline__ void split2(float a, float b, uint32_t &hi, uint32_t &lo) {
    __nv_bfloat16 ha = __float2bfloat16_rn(a);
    __nv_bfloat16 hb = __float2bfloat16_rn(b);
    __nv_bfloat16 la = __float2bfloat16_rn(a - __bfloat162float(ha));
    __nv_bfloat16 lb = __float2bfloat16_rn(b - __bfloat162float(hb));
    __nv_bfloat162 hp = __halves2bfloat162(ha, hb);
    __nv_bfloat162 lp = __halves2bfloat162(la, lb);
    hi = *(uint32_t*)&hp;
    lo = *(uint32_t*)&lp;
}

// ---------------------------------------------------------------------------
// Kernel 1: conv1 (proven round-1 form: 41.6us)
// ---------------------------------------------------------------------------
__global__ __launch_bounds__(256) void conv1_kernel(
    const float* __restrict__ x, const float* __restrict__ w,
    const float* __restrict__ bias)
{
    __shared__ __align__(16) float w_sh[27][64];
    __shared__ float b_sh[64];
    int tid = threadIdx.x;
    for (int idx = tid; idx < 64*27; idx += 256) {
        int oc = idx / 27, r = idx % 27;
        w_sh[r][oc] = w[idx];
    }
    if (tid < 64) b_sh[tid] = bias[tid];
    __syncthreads();

    int px  = blockIdx.x * 256 + tid;
    int b   = px >> 16;
    int rem = px & 0xFFFF;
    int oy  = rem >> 8, ox = rem & 255;

    float in[27];
    #pragma unroll
    for (int c = 0; c < 3; c++)
        #pragma unroll
        for (int ky = 0; ky < 3; ky++)
            #pragma unroll
            for (int kx = 0; kx < 3; kx++) {
                int iy = oy + ky - 1, ix = ox + kx - 1;
                bool ok = (iy >= 0 && iy < HH && ix >= 0 && ix < WW);
                in[c*9 + ky*3 + kx] = ok ? __ldg(&x[((b*3 + c)*HH + iy)*WW + ix]) : 0.f;
            }

    float acc[64];
    #pragma unroll
    for (int oc = 0; oc < 64; oc++) acc[oc] = b_sh[oc];

    #pragma unroll
    for (int r = 0; r < 27; r++) {
        float v = in[r];
        #pragma unroll
        for (int oc = 0; oc < 64; oc += 4) {
            float4 wv = *(const float4*)&w_sh[r][oc];
            acc[oc+0] += v * wv.x;  acc[oc+1] += v * wv.y;
            acc[oc+2] += v * wv.z;  acc[oc+3] += v * wv.w;
        }
    }
    int pix = oy*WW + ox;
    #pragma unroll
    for (int oc = 0; oc < 64; oc++)
        g_feat[(b*CC + oc)*HWP + pix] = acc[oc];
}

// ---------------------------------------------------------------------------
// Kernel 1.5a: build deform B fragments (split bf16), frag-linear
// ---------------------------------------------------------------------------
__global__ void wfrag_kernel(const float* __restrict__ dw)
{
    int idx = blockIdx.x * 256 + threadIdx.x;
    if (idx >= 9*4*4*32*4) return;
    int r    = idx & 3;
    int l    = (idx >> 2) & 31;
    int ntp  = (idx >> 7) & 3;
    int ks   = (idx >> 9) & 3;
    int k    = idx >> 11;
    int nt   = ntp*2 + (r >> 1);
    int n    = nt*8 + (l >> 2);
    int c    = 2*(l & 3) + (r & 1)*8 + 16*ks;

    float w0 = dw[(n*64 + c    )*9 + k];
    float w1 = dw[(n*64 + c + 1)*9 + k];
    uint32_t hi, lo;
    split2(w0, w1, hi, lo);
    g_wfragH[idx] = hi;
    g_wfragL[idx] = lo;
}

// ---------------------------------------------------------------------------
// Kernel 1.5b: build offset-conv B fragments (N padded to 32 with zeros)
// ---------------------------------------------------------------------------
__global__ void ofrag_kernel(const float* __restrict__ ow)
{
    int idx = blockIdx.x * 256 + threadIdx.x;
    if (idx >= 9*4*2*32*4) return;
    int r    = idx & 3;
    int l    = (idx >> 2) & 31;
    int ntp  = (idx >> 7) & 1;
    int ks   = (idx >> 8) & 3;
    int k    = idx >> 10;
    int nt   = ntp*2 + (r >> 1);
    int n    = nt*8 + (l >> 2);
    int c    = 2*(l & 3) + (r & 1)*8 + 16*ks;

    float w0 = (n < KOFF) ? ow[(n*64 + c    )*9 + k] : 0.f;
    float w1 = (n < KOFF) ? ow[(n*64 + c + 1)*9 + k] : 0.f;
    uint32_t hi, lo;
    split2(w0, w1, hi, lo);
    g_ofragH[idx] = hi;
    g_ofragL[idx] = lo;
}

// ---------------------------------------------------------------------------
// Kernel 2: offset conv — HMMA, 3x row reuse + uint4 STS staging
// ---------------------------------------------------------------------------
#define OS_HI 0
#define OS_LO 33280                    // 260 slots * 128B
#define OBIAS_OFF 66560
#define OSMEM_TOT (66560 + 128)

__global__ __launch_bounds__(256, 2) void offconv_mma_kernel(
    const float* __restrict__ obias)
{
    extern __shared__ char smem[];
    uint32_t sb = smem_u32(smem);
    int tid = threadIdx.x;
    int wid = tid >> 5, lane = tid & 31;

    if (tid < KOFF) ((float*)(smem + OBIAS_OFF))[tid] = __ldg(&obias[tid]);

    int b  = blockIdx.x >> 8;
    int oy = blockIdx.x & 255;
    int ox = tid;
    int rot = (ox >> 3) & 7;            // ic-group rotation over 8 groups of 8

    const float* fb = g_feat + b*CC*HWP;

    float acc[32];
    #pragma unroll
    for (int i = 0; i < 32; i++) acc[i] = 0.f;

    uint32_t acol = (uint32_t)((lane >> 4) * 16);

    // zero the pad slots 0 and 257 (stay zero for all 3 rows)
    if (tid < 64) {
        int slot = (tid < 32) ? 0 : 257;
        int t = tid & 31;
        uint32_t sw = SWZ((uint32_t)(slot*128 + t*4));
        *(uint32_t*)(smem + OS_HI + sw) = 0u;
        *(uint32_t*)(smem + OS_LO + sw) = 0u;
    }

    #pragma unroll 1
    for (int i = 0; i < 3; i++) {
        int iy = oy + i - 1;
        bool ok = (iy >= 0 && iy < HH);
        int pix_s = ok ? (iy*WW + ox) : 0;

        __syncthreads();                // pad/prev-MMA readers done

        // stage this row once (slot ox+1), 8 ic per group, uint4 STS
        #pragma unroll 1
        for (int g = 0; g < 8; g++) {
            int ic = ((g + rot) & 7) * 8;
            float s[8];
            #pragma unroll
            for (int t = 0; t < 8; t++)
                s[t] = ok ? __ldg(fb + (ic + t)*HWP + pix_s) : 0.f;
            uint32_t hi[4], lo[4];
            #pragma unroll
            for (int q = 0; q < 4; q++)
                split2(s[2*q], s[2*q+1], hi[q], lo[q]);
            uint32_t sw = SWZ((uint32_t)((ox+1)*128 + ic*2));   // 16B-aligned
            *(uint4*)(smem + OS_HI + sw) = make_uint4(hi[0], hi[1], hi[2], hi[3]);
            *(uint4*)(smem + OS_LO + sw) = make_uint4(lo[0], lo[1], lo[2], lo[3]);
        }

        __syncthreads();

        // 3 taps from this one staged row: j-shift = +j*128B on A address
        #pragma unroll
        for (int j = 0; j < 3; j++) {
            int k = i*3 + j;
            uint32_t arow0 = (uint32_t)(wid*32 + (lane & 15) + j) * 128;
            uint32_t arow1 = arow0 + 16*128;
            #pragma unroll
            for (int ks = 0; ks < 4; ks++) {
                uint32_t kb = (uint32_t)(ks*32);
                uint32_t aH0[4], aH1[4], aL0[4], aL1[4];
                ldsm4(aH0, sb + OS_HI + SWZ(arow0 + kb + acol));
                ldsm4(aH1, sb + OS_HI + SWZ(arow1 + kb + acol));
                ldsm4(aL0, sb + OS_LO + SWZ(arow0 + kb + acol));
                ldsm4(aL1, sb + OS_LO + SWZ(arow1 + kb + acol));
                #pragma unroll
                for (int ntp = 0; ntp < 2; ntp++) {
                    int fidx = (((k*4 + ks)*2 + ntp)*32 + lane)*4;
                    uint4 bhv = *(const uint4*)&g_ofragH[fidx];
                    uint4 blv = *(const uint4*)&g_ofragL[fidx];
                    uint32_t bh[4] = {bhv.x, bhv.y, bhv.z, bhv.w};
                    uint32_t bl[4] = {blv.x, blv.y, blv.z, blv.w};
                    float* c00 = acc + (0*4 + 2*ntp    )*4;
                    float* c10 = acc + (1*4 + 2*ntp    )*4;
                    float* c01 = acc + (0*4 + 2*ntp + 1)*4;
                    float* c11 = acc + (1*4 + 2*ntp + 1)*4;
                    mma16816(c00, aH0, bh);     mma16816(c10, aH1, bh);
                    mma16816(c01, aH0, bh + 2); mma16816(c11, aH1, bh + 2);
                    mma16816(c00, aL0, bh);     mma16816(c10, aL1, bh);
                    mma16816(c01, aL0, bh + 2); mma16816(c11, aL1, bh + 2);
                    mma16816(c00, aH0, bl);     mma16816(c10, aH1, bl);
                    mma16816(c01, aH0, bl + 2); mma16816(c11, aH1, bl + 2);
                }
            }
        }
    }

    // epilogue: frags -> smem [n][px] (260 pad) -> coalesced g_off stores
    __syncthreads();
    float* ds = (float*)smem;           // 32 x 260 floats = 33280 B
    {
        int mrow = wid*32 + (lane >> 2);
        int ncol = 2*(lane & 3);
        #pragma unroll
        for (int mt = 0; mt < 2; mt++) {
            int m = mrow + mt*16;
            #pragma unroll
            for (int nt = 0; nt < 4; nt++) {
                int n = nt*8 + ncol;
                const float* c = acc + (mt*4 + nt)*4;
                ds[ n   *260 + m    ] = c[0];
                ds[(n+1)*260 + m    ] = c[1];
                ds[ n   *260 + m + 8] = c[2];
                ds[(n+1)*260 + m + 8] = c[3];
            }
        }
    }
    __syncthreads();
    {
        const float* bs = (const float*)(smem + OBIAS_OFF);
        int row_base = oy*WW;
        float* go = g_off + b*KOFF*HWP;
        #pragma unroll
        for (int o = 0; o < KOFF; o++)
            go[o*HWP + row_base + tid] = ds[o*260 + tid] + bs[o];
    }
}

// ---------------------------------------------------------------------------
// Kernel 3: deformable conv — HMMA + uint4 STS staging (round-14: ~281us)
// with offset/Samp hoisted above the per-tap barrier
// ---------------------------------------------------------------------------
#define S_HI_OFF 0
#define S_LO_OFF 32768
#define BIAS_OFF 66560
#define SMEM3_TOT (66560 + 256)

struct Samp { float w00, w01, w10, w11; int i00, i01, i10, i11; };

__device__ __forceinline__ Samp make_samp(float sy, float sx)
{
    float y0f = floorf(sy), x0f = floorf(sx);
    float dy = sy - y0f,    dx = sx - x0f;

    bool vy0 = (y0f       >= 0.f) && (y0f       <= (float)(HH-1));
    bool vy1 = (y0f + 1.f >= 0.f) && (y0f + 1.f <= (float)(HH-1));
    bool vx0 = (x0f       >= 0.f) && (x0f       <= (float)(WW-1));
    bool vx1 = (x0f + 1.f >= 0.f) && (x0f + 1.f <= (float)(WW-1));

    int y0 = (int)fminf(fmaxf(y0f,       0.f), (float)(HH-1));
    int y1 = (int)fminf(fmaxf(y0f + 1.f, 0.f), (float)(HH-1));
    int x0 = (int)fminf(fmaxf(x0f,       0.f), (float)(WW-1));
    int x1 = (int)fminf(fmaxf(x0f + 1.f, 0.f), (float)(WW-1));

    Samp s;
    s.w00 = (1.f-dy)*(1.f-dx) * ((vy0 && vx0) ? 1.f : 0.f);
    s.w01 = (1.f-dy)*dx       * ((vy0 && vx1) ? 1.f : 0.f);
    s.w10 = dy*(1.f-dx)       * ((vy1 && vx0) ? 1.f : 0.f);
    s.w11 = dy*dx             * ((vy1 && vx1) ? 1.f : 0.f);
    s.i00 = y0*WW + x0;  s.i01 = y0*WW + x1;
    s.i10 = y1*WW + x0;  s.i11 = y1*WW + x1;
    return s;
}

__global__ __launch_bounds__(256, 2) void deform_mma_kernel(
    const float* __restrict__ dbias, float* __restrict__ out)
{
    extern __shared__ char smem[];
    uint32_t sb = smem_u32(smem);
    int tid = threadIdx.x;
    int wid = tid >> 5, lane = tid & 31;

    if (tid < 64) ((float*)(smem + BIAS_OFF))[tid] = __ldg(&dbias[tid]);

    int b  = blockIdx.x >> 8;
    int oy = blockIdx.x & 255;
    int ox = tid;
    int pix = oy*WW + ox;

    const float* fb = g_feat + b*CC*HWP;
    const float* ob = g_off  + b*KOFF*HWP;

    float acc[64];
    #pragma unroll
    for (int i = 0; i < 64; i++) acc[i] = 0.f;

    uint32_t arow0 = (uint32_t)(wid*32 + (lane & 15)) * 128;
    uint32_t arow1 = arow0 + 16*128;
    uint32_t acol  = (uint32_t)((lane >> 4) * 16);

    #pragma unroll 1
    for (int k = 0; k < 9; k++) {
        // offset load + Samp: no smem dependence -> overlap with barrier wait
        int i = k / 3, j = k % 3;
        float offy = __ldg(ob + (2*k    )*HWP + pix);
        float offx = __ldg(ob + (2*k + 1)*HWP + pix);
        Samp S = make_samp((float)(oy - 1 + i) + offy,
                           (float)(ox - 1 + j) + offx);

        __syncthreads();

        // gather 64 ic, 8 ic per group, one uint4 STS per hi/lo per group
        #pragma unroll 1
        for (int g = 0; g < 8; g++) {
            int ic = g*8;
            float s[8];
            #pragma unroll
            for (int t = 0; t < 8; t++) {
                const float* p = fb + (ic + t)*HWP;
                s[t] = S.w00*__ldg(p + S.i00) + S.w01*__ldg(p + S.i01)
                     + S.w10*__ldg(p + S.i10) + S.w11*__ldg(p + S.i11);
            }
            uint32_t hi[4], lo[4];
            #pragma unroll
            for (int q = 0; q < 4; q++)
                split2(s[2*q], s[2*q+1], hi[q], lo[q]);
            uint32_t sw = SWZ((uint32_t)(ox*128 + ic*2));   // 16B-aligned
            *(uint4*)(smem + S_HI_OFF + sw) = make_uint4(hi[0], hi[1], hi[2], hi[3]);
            *(uint4*)(smem + S_LO_OFF + sw) = make_uint4(lo[0], lo[1], lo[2], lo[3]);
        }

        __syncthreads();

        #pragma unroll
        for (int ks = 0; ks < 4; ks++) {
            uint32_t kb = (uint32_t)(ks*32);
            uint32_t aH0[4], aH1[4], aL0[4], aL1[4];
            ldsm4(aH0, sb + S_HI_OFF + SWZ(arow0 + kb + acol));
            ldsm4(aH1, sb + S_HI_OFF + SWZ(arow1 + kb + acol));
            ldsm4(aL0, sb + S_LO_OFF + SWZ(arow0 + kb + acol));
            ldsm4(aL1, sb + S_LO_OFF + SWZ(arow1 + kb + acol));
            #pragma unroll
            for (int ntp = 0; ntp < 4; ntp++) {
                int fidx = (((k*4 + ks)*4 + ntp)*32 + lane)*4;
                uint4 bhv = *(const uint4*)&g_wfragH[fidx];
                uint4 blv = *(const uint4*)&g_wfragL[fidx];
                uint32_t bh[4] = {bhv.x, bhv.y, bhv.z, bhv.w};
                uint32_t bl[4] = {blv.x, blv.y, blv.z, blv.w};
                float* c00 = acc + (0*8 + 2*ntp    )*4;
                float* c10 = acc + (1*8 + 2*ntp    )*4;
                float* c01 = acc + (0*8 + 2*ntp + 1)*4;
                float* c11 = acc + (1*8 + 2*ntp + 1)*4;
                mma16816(c00, aH0, bh);     mma16816(c10, aH1, bh);
                mma16816(c01, aH0, bh + 2); mma16816(c11, aH1, bh + 2);
                mma16816(c00, aL0, bh);     mma16816(c10, aL1, bh);
                mma16816(c01, aL0, bh + 2); mma16816(c11, aL1, bh + 2);
                mma16816(c00, aH0, bl);     mma16816(c10, aH1, bl);
                mma16816(c01, aH0, bl + 2); mma16816(c11, aH1, bl + 2);
            }
        }
    }

    __syncthreads();
    float* ds = (float*)smem;
    {
        int mrow = wid*32 + (lane >> 2);
        int ncol = 2*(lane & 3);
        #pragma unroll
        for (int mt = 0; mt < 2; mt++) {
            int m = mrow + mt*16;
            #pragma unroll
            for (int nt = 0; nt < 8; nt++) {
                int n = nt*8 + ncol;
                const float* c = acc + (mt*8 + nt)*4;
                ds[ n   *260 + m    ] = c[0];
                ds[(n+1)*260 + m    ] = c[1];
                ds[ n   *260 + m + 8] = c[2];
                ds[(n+1)*260 + m + 8] = c[3];
            }
        }
    }
    __syncthreads();
    {
        const float* bs = (const float*)(smem + BIAS_OFF);
        int row_base = oy*WW;
        #pragma unroll
        for (int t = 0; t < 8; t++) {
            int oc = wid*8 + t;
            float bv = bs[oc];
            #pragma unroll
            for (int h = 0; h < 2; h++) {
                int p4 = h*128 + lane*4;
                float4 v = *(const float4*)&ds[oc*260 + p4];
                v.x += bv; v.y += bv; v.z += bv; v.w += bv;
                *(float4*)&out[(b*CC + oc)*HWP + row_base + p4] = v;
            }
        }
    }
}

// ---------------------------------------------------------------------------
extern "C" void kernel_launch(void* const* d_in, const int* in_sizes, int n_in,
                              void* d_out, int out_size)
{
    const float* x      = (const float*)d_in[0];
    const float* conv_w = (const float*)d_in[1];
    const float* conv_b = (const float*)d_in[2];
    const float* off_w  = (const float*)d_in[3];
    const float* off_b  = (const float*)d_in[4];
    const float* dw     = (const float*)d_in[5];
    const float* db     = (const float*)d_in[6];
    float* out = (float*)d_out;

    const int blocks = BB*HH*WW / 256;   // 1024

    wfrag_kernel  <<<72, 256>>>(dw);
    ofrag_kernel  <<<36, 256>>>(off_w);
    conv1_kernel  <<<blocks, 256>>>(x, conv_w, conv_b);

    cudaFuncSetAttribute(offconv_mma_kernel,
                         cudaFuncAttributeMaxDynamicSharedMemorySize, OSMEM_TOT);
    offconv_mma_kernel<<<BB*HH, 256, OSMEM_TOT>>>(off_b);

    cudaFuncSetAttribute(deform_mma_kernel,
                         cudaFuncAttributeMaxDynamicSharedMemorySize, SMEM3_TOT);
    deform_mma_kernel<<<BB*HH, 256, SMEM3_TOT>>>(db, out);
}

// round 17
// speedup vs baseline: 1.0160x; 1.0160x over previous
#include <cuda_runtime.h>
#include <cuda_bf16.h>
#include <cstdint>

// Problem constants
#define HH 256
#define WW 256
#define BB 4
#define CC 64
#define KOFF 18
#define HWP (HH*WW)

// Scratch (device-global)
__device__ float g_feat[BB*CC*HH*WW];            // 64 MiB
__device__ float g_off [BB*KOFF*HH*WW];          // 18 MiB
// deform weights in per-lane HMMA fragment order
__device__ uint32_t g_wfragH[9*4*4*32*4];
__device__ uint32_t g_wfragL[9*4*4*32*4];
// offset-conv weights, frag order (N padded 18->32; only n<24 consumed)
__device__ uint32_t g_ofragH[9*4*2*32*4];
__device__ uint32_t g_ofragL[9*4*2*32*4];

typedef unsigned long long u64;

// ---------------------------------------------------------------------------
// helpers
// ---------------------------------------------------------------------------
__device__ __forceinline__ uint32_t smem_u32(const void* p) {
    uint32_t a;
    asm("{ .reg .u64 t; cvta.to.shared.u64 t, %1; cvt.u32.u64 %0, t; }"
        : "=r"(a) : "l"(p));
    return a;
}
#define SWZ(b) ((b) ^ (((b) >> 3) & 0x70))

__device__ __forceinline__ void ldsm4(uint32_t* r, uint32_t addr) {
    asm volatile("ldmatrix.sync.aligned.m8n8.x4.shared.b16 {%0,%1,%2,%3}, [%4];"
        : "=r"(r[0]), "=r"(r[1]), "=r"(r[2]), "=r"(r[3]) : "r"(addr));
}
__device__ __forceinline__ void mma16816(float* d, const uint32_t* a, const uint32_t* b) {
    asm volatile(
        "mma.sync.aligned.m16n8k16.row.col.f32.bf16.bf16.f32 "
        "{%0,%1,%2,%3}, {%4,%5,%6,%7}, {%8,%9}, {%0,%1,%2,%3};"
        : "+f"(d[0]), "+f"(d[1]), "+f"(d[2]), "+f"(d[3])
        : "r"(a[0]), "r"(a[1]), "r"(a[2]), "r"(a[3]), "r"(b[0]), "r"(b[1]));
}

// split-bf16 pack helper: 2 floats -> (hi bf16x2, lo bf16x2)
__device__ __forceinline__ void split2(float a, float b, uint32_t &hi, uint32_t &lo) {
    __nv_bfloat16 ha = __float2bfloat16_rn(a);
    __nv_bfloat16 hb = __float2bfloat16_rn(b);
    __nv_bfloat16 la = __float2bfloat16_rn(a - __bfloat162float(ha));
    __nv_bfloat16 lb = __float2bfloat16_rn(b - __bfloat162float(hb));
    __nv_bfloat162 hp = __halves2bfloat162(ha, hb);
    __nv_bfloat162 lp = __halves2bfloat162(la, lb);
    hi = *(uint32_t*)&hp;
    lo = *(uint32_t*)&lp;
}

// ---------------------------------------------------------------------------
// Kernel 1: conv1 (proven round-1 form: 41.6us)
// ---------------------------------------------------------------------------
__global__ __launch_bounds__(256) void conv1_kernel(
    const float* __restrict__ x, const float* __restrict__ w,
    const float* __restrict__ bias)
{
    __shared__ __align__(16) float w_sh[27][64];
    __shared__ float b_sh[64];
    int tid = threadIdx.x;
    for (int idx = tid; idx < 64*27; idx += 256) {
        int oc = idx / 27, r = idx % 27;
        w_sh[r][oc] = w[idx];
    }
    if (tid < 64) b_sh[tid] = bias[tid];
    __syncthreads();

    int px  = blockIdx.x * 256 + tid;
    int b   = px >> 16;
    int rem = px & 0xFFFF;
    int oy  = rem >> 8, ox = rem & 255;

    float in[27];
    #pragma unroll
    for (int c = 0; c < 3; c++)
        #pragma unroll
        for (int ky = 0; ky < 3; ky++)
            #pragma unroll
            for (int kx = 0; kx < 3; kx++) {
                int iy = oy + ky - 1, ix = ox + kx - 1;
                bool ok = (iy >= 0 && iy < HH && ix >= 0 && ix < WW);
                in[c*9 + ky*3 + kx] = ok ? __ldg(&x[((b*3 + c)*HH + iy)*WW + ix]) : 0.f;
            }

    float acc[64];
    #pragma unroll
    for (int oc = 0; oc < 64; oc++) acc[oc] = b_sh[oc];

    #pragma unroll
    for (int r = 0; r < 27; r++) {
        float v = in[r];
        #pragma unroll
        for (int oc = 0; oc < 64; oc += 4) {
            float4 wv = *(const float4*)&w_sh[r][oc];
            acc[oc+0] += v * wv.x;  acc[oc+1] += v * wv.y;
            acc[oc+2] += v * wv.z;  acc[oc+3] += v * wv.w;
        }
    }
    int pix = oy*WW + ox;
    #pragma unroll
    for (int oc = 0; oc < 64; oc++)
        g_feat[(b*CC + oc)*HWP + pix] = acc[oc];
}

// ---------------------------------------------------------------------------
// Kernel 1.5a: build deform B fragments (split bf16), frag-linear
// ---------------------------------------------------------------------------
__global__ void wfrag_kernel(const float* __restrict__ dw)
{
    int idx = blockIdx.x * 256 + threadIdx.x;
    if (idx >= 9*4*4*32*4) return;
    int r    = idx & 3;
    int l    = (idx >> 2) & 31;
    int ntp  = (idx >> 7) & 3;
    int ks   = (idx >> 9) & 3;
    int k    = idx >> 11;
    int nt   = ntp*2 + (r >> 1);
    int n    = nt*8 + (l >> 2);
    int c    = 2*(l & 3) + (r & 1)*8 + 16*ks;

    float w0 = dw[(n*64 + c    )*9 + k];
    float w1 = dw[(n*64 + c + 1)*9 + k];
    uint32_t hi, lo;
    split2(w0, w1, hi, lo);
    g_wfragH[idx] = hi;
    g_wfragL[idx] = lo;
}

// ---------------------------------------------------------------------------
// Kernel 1.5b: build offset-conv B fragments (N padded to 32 with zeros)
// ---------------------------------------------------------------------------
__global__ void ofrag_kernel(const float* __restrict__ ow)
{
    int idx = blockIdx.x * 256 + threadIdx.x;
    if (idx >= 9*4*2*32*4) return;
    int r    = idx & 3;
    int l    = (idx >> 2) & 31;
    int ntp  = (idx >> 7) & 1;
    int ks   = (idx >> 8) & 3;
    int k    = idx >> 10;
    int nt   = ntp*2 + (r >> 1);
    int n    = nt*8 + (l >> 2);
    int c    = 2*(l & 3) + (r & 1)*8 + 16*ks;

    float w0 = (n < KOFF) ? ow[(n*64 + c    )*9 + k] : 0.f;
    float w1 = (n < KOFF) ? ow[(n*64 + c + 1)*9 + k] : 0.f;
    uint32_t hi, lo;
    split2(w0, w1, hi, lo);
    g_ofragH[idx] = hi;
    g_ofragL[idx] = lo;
}

// ---------------------------------------------------------------------------
// Kernel 2: offset conv — HMMA, 3x row reuse, 3-pass split-bf16, N trimmed
// to 24 (ntp=1 is a half-tile: n16-23 only; n24-31 are all-zero, skipped)
// ---------------------------------------------------------------------------
#define OS_HI 0
#define OS_LO 33280                    // 260 slots * 128B
#define OBIAS_OFF 66560
#define OSMEM_TOT (66560 + 128)

__global__ __launch_bounds__(256, 2) void offconv_mma_kernel(
    const float* __restrict__ obias)
{
    extern __shared__ char smem[];
    uint32_t sb = smem_u32(smem);
    int tid = threadIdx.x;
    int wid = tid >> 5, lane = tid & 31;

    if (tid < KOFF) ((float*)(smem + OBIAS_OFF))[tid] = __ldg(&obias[tid]);

    int b  = blockIdx.x >> 8;
    int oy = blockIdx.x & 255;
    int ox = tid;
    int rot = (ox >> 3) & 15;           // bank-conflict-avoiding ic-group rotation

    const float* fb = g_feat + b*CC*HWP;

    float acc[32];
    #pragma unroll
    for (int i = 0; i < 32; i++) acc[i] = 0.f;

    uint32_t acol = (uint32_t)((lane >> 4) * 16);

    // zero the pad slots 0 and 257 (stay zero for all 3 rows)
    if (tid < 64) {
        int slot = (tid < 32) ? 0 : 257;
        int t = tid & 31;
        uint32_t sw = SWZ((uint32_t)(slot*128 + t*4));
        *(uint32_t*)(smem + OS_HI + sw) = 0u;
        *(uint32_t*)(smem + OS_LO + sw) = 0u;
    }

    #pragma unroll 1
    for (int i = 0; i < 3; i++) {
        __syncthreads();                // pad/prev-MMA readers done

        int iy = oy + i - 1;
        bool ok = (iy >= 0 && iy < HH);
        int pix_s = ok ? (iy*WW + ox) : 0;

        // stage this row once (slot ox+1), split bf16
        #pragma unroll 2
        for (int g = 0; g < 16; g++) {
            int ic = ((g + rot) & 15) * 4;
            float s0 = ok ? __ldg(fb + (ic+0)*HWP + pix_s) : 0.f;
            float s1 = ok ? __ldg(fb + (ic+1)*HWP + pix_s) : 0.f;
            float s2 = ok ? __ldg(fb + (ic+2)*HWP + pix_s) : 0.f;
            float s3 = ok ? __ldg(fb + (ic+3)*HWP + pix_s) : 0.f;
            uint32_t hiA, loA, hiB, loB;
            split2(s0, s1, hiA, loA);
            split2(s2, s3, hiB, loB);
            uint32_t sw = SWZ((uint32_t)((ox+1)*128 + ic*2));
            *(uint2*)(smem + OS_HI + sw) = make_uint2(hiA, hiB);
            *(uint2*)(smem + OS_LO + sw) = make_uint2(loA, loB);
        }

        __syncthreads();

        // 3 taps from this one staged row: j-shift = +j*128B on A address
        #pragma unroll
        for (int j = 0; j < 3; j++) {
            int k = i*3 + j;
            uint32_t arow0 = (uint32_t)(wid*32 + (lane & 15) + j) * 128;
            uint32_t arow1 = arow0 + 16*128;
            #pragma unroll
            for (int ks = 0; ks < 4; ks++) {
                uint32_t kb = (uint32_t)(ks*32);
                uint32_t aH0[4], aH1[4], aL0[4], aL1[4];
                ldsm4(aH0, sb + OS_HI + SWZ(arow0 + kb + acol));
                ldsm4(aH1, sb + OS_HI + SWZ(arow1 + kb + acol));
                ldsm4(aL0, sb + OS_LO + SWZ(arow0 + kb + acol));
                ldsm4(aL1, sb + OS_LO + SWZ(arow1 + kb + acol));

                // ntp = 0: full n16 pair (n0..15)
                {
                    int fidx = (((k*4 + ks)*2 + 0)*32 + lane)*4;
                    uint4 bhv = *(const uint4*)&g_ofragH[fidx];
                    uint4 blv = *(const uint4*)&g_ofragL[fidx];
                    uint32_t bh[4] = {bhv.x, bhv.y, bhv.z, bhv.w};
                    uint32_t bl[4] = {blv.x, blv.y, blv.z, blv.w};
                    float* c00 = acc + (0*4 + 0)*4;
                    float* c10 = acc + (1*4 + 0)*4;
                    float* c01 = acc + (0*4 + 1)*4;
                    float* c11 = acc + (1*4 + 1)*4;
                    mma16816(c00, aH0, bh);     mma16816(c10, aH1, bh);
                    mma16816(c01, aH0, bh + 2); mma16816(c11, aH1, bh + 2);
                    mma16816(c00, aL0, bh);     mma16816(c10, aL1, bh);
                    mma16816(c01, aL0, bh + 2); mma16816(c11, aL1, bh + 2);
                    mma16816(c00, aH0, bl);     mma16816(c10, aH1, bl);
                    mma16816(c01, aH0, bl + 2); mma16816(c11, aH1, bl + 2);
                }
                // ntp = 1 half-tile: n16..23 only (n24..31 are all zero)
                {
                    int fidx = (((k*4 + ks)*2 + 1)*32 + lane)*4;
                    uint2 bhv = *(const uint2*)&g_ofragH[fidx];
                    uint2 blv = *(const uint2*)&g_ofragL[fidx];
                    uint32_t bh[2] = {bhv.x, bhv.y};
                    uint32_t bl[2] = {blv.x, blv.y};
                    float* c00 = acc + (0*4 + 2)*4;
                    float* c10 = acc + (1*4 + 2)*4;
                    mma16816(c00, aH0, bh);  mma16816(c10, aH1, bh);
                    mma16816(c00, aL0, bh);  mma16816(c10, aL1, bh);
                    mma16816(c00, aH0, bl);  mma16816(c10, aH1, bl);
                }
            }
        }
    }

    // epilogue: frags -> smem [n][px] (260 pad) -> coalesced g_off stores
    __syncthreads();
    float* ds = (float*)smem;           // 32 x 260 floats = 33280 B
    {
        int mrow = wid*32 + (lane >> 2);
        int ncol = 2*(lane & 3);
        #pragma unroll
        for (int mt = 0; mt < 2; mt++) {
            int m = mrow + mt*16;
            #pragma unroll
            for (int nt = 0; nt < 3; nt++) {      // only n0..23 materialized
                int n = nt*8 + ncol;
                const float* c = acc + (mt*4 + nt)*4;
                ds[ n   *260 + m    ] = c[0];
                ds[(n+1)*260 + m    ] = c[1];
                ds[ n   *260 + m + 8] = c[2];
                ds[(n+1)*260 + m + 8] = c[3];
            }
        }
    }
    __syncthreads();
    {
        const float* bs = (const float*)(smem + OBIAS_OFF);
        int row_base = oy*WW;
        float* go = g_off + b*KOFF*HWP;
        #pragma unroll
        for (int o = 0; o < KOFF; o++)
            go[o*HWP + row_base + tid] = ds[o*260 + tid] + bs[o];
    }
}

// ---------------------------------------------------------------------------
// Kernel 3: deformable conv — HMMA + uint4 STS staging (round-14 proven form)
// ---------------------------------------------------------------------------
#define S_HI_OFF 0
#define S_LO_OFF 32768
#define BIAS_OFF 66560
#define SMEM3_TOT (66560 + 256)

struct Samp { float w00, w01, w10, w11; int i00, i01, i10, i11; };

__device__ __forceinline__ Samp make_samp(float sy, float sx)
{
    float y0f = floorf(sy), x0f = floorf(sx);
    float dy = sy - y0f,    dx = sx - x0f;

    bool vy0 = (y0f       >= 0.f) && (y0f       <= (float)(HH-1));
    bool vy1 = (y0f + 1.f >= 0.f) && (y0f + 1.f <= (float)(HH-1));
    bool vx0 = (x0f       >= 0.f) && (x0f       <= (float)(WW-1));
    bool vx1 = (x0f + 1.f >= 0.f) && (x0f + 1.f <= (float)(WW-1));

    int y0 = (int)fminf(fmaxf(y0f,       0.f), (float)(HH-1));
    int y1 = (int)fminf(fmaxf(y0f + 1.f, 0.f), (float)(HH-1));
    int x0 = (int)fminf(fmaxf(x0f,       0.f), (float)(WW-1));
    int x1 = (int)fminf(fmaxf(x0f + 1.f, 0.f), (float)(WW-1));

    Samp s;
    s.w00 = (1.f-dy)*(1.f-dx) * ((vy0 && vx0) ? 1.f : 0.f);
    s.w01 = (1.f-dy)*dx       * ((vy0 && vx1) ? 1.f : 0.f);
    s.w10 = dy*(1.f-dx)       * ((vy1 && vx0) ? 1.f : 0.f);
    s.w11 = dy*dx             * ((vy1 && vx1) ? 1.f : 0.f);
    s.i00 = y0*WW + x0;  s.i01 = y0*WW + x1;
    s.i10 = y1*WW + x0;  s.i11 = y1*WW + x1;
    return s;
}

__global__ __launch_bounds__(256, 2) void deform_mma_kernel(
    const float* __restrict__ dbias, float* __restrict__ out)
{
    extern __shared__ char smem[];
    uint32_t sb = smem_u32(smem);
    int tid = threadIdx.x;
    int wid = tid >> 5, lane = tid & 31;

    if (tid < 64) ((float*)(smem + BIAS_OFF))[tid] = __ldg(&dbias[tid]);

    int b  = blockIdx.x >> 8;
    int oy = blockIdx.x & 255;
    int ox = tid;
    int pix = oy*WW + ox;

    const float* fb = g_feat + b*CC*HWP;
    const float* ob = g_off  + b*KOFF*HWP;

    float acc[64];
    #pragma unroll
    for (int i = 0; i < 64; i++) acc[i] = 0.f;

    uint32_t arow0 = (uint32_t)(wid*32 + (lane & 15)) * 128;
    uint32_t arow1 = arow0 + 16*128;
    uint32_t acol  = (uint32_t)((lane >> 4) * 16);

    #pragma unroll 1
    for (int k = 0; k < 9; k++) {
        __syncthreads();

        int i = k / 3, j = k % 3;
        float offy = __ldg(ob + (2*k    )*HWP + pix);
        float offx = __ldg(ob + (2*k + 1)*HWP + pix);
        Samp S = make_samp((float)(oy - 1 + i) + offy,
                           (float)(ox - 1 + j) + offx);

        // gather 64 ic, 8 ic per group, one uint4 STS per hi/lo per group
        #pragma unroll 1
        for (int g = 0; g < 8; g++) {
            int ic = g*8;
            float s[8];
            #pragma unroll
            for (int t = 0; t < 8; t++) {
                const float* p = fb + (ic + t)*HWP;
                s[t] = S.w00*__ldg(p + S.i00) + S.w01*__ldg(p + S.i01)
                     + S.w10*__ldg(p + S.i10) + S.w11*__ldg(p + S.i11);
            }
            uint32_t hi[4], lo[4];
            #pragma unroll
            for (int q = 0; q < 4; q++)
                split2(s[2*q], s[2*q+1], hi[q], lo[q]);
            uint32_t sw = SWZ((uint32_t)(ox*128 + ic*2));   // 16B-aligned
            *(uint4*)(smem + S_HI_OFF + sw) = make_uint4(hi[0], hi[1], hi[2], hi[3]);
            *(uint4*)(smem + S_LO_OFF + sw) = make_uint4(lo[0], lo[1], lo[2], lo[3]);
        }

        __syncthreads();

        #pragma unroll
        for (int ks = 0; ks < 4; ks++) {
            uint32_t kb = (uint32_t)(ks*32);
            uint32_t aH0[4], aH1[4], aL0[4], aL1[4];
            ldsm4(aH0, sb + S_HI_OFF + SWZ(arow0 + kb + acol));
            ldsm4(aH1, sb + S_HI_OFF + SWZ(arow1 + kb + acol));
            ldsm4(aL0, sb + S_LO_OFF + SWZ(arow0 + kb + acol));
            ldsm4(aL1, sb + S_LO_OFF + SWZ(arow1 + kb + acol));
            #pragma unroll
            for (int ntp = 0; ntp < 4; ntp++) {
                int fidx = (((k*4 + ks)*4 + ntp)*32 + lane)*4;
                uint4 bhv = *(const uint4*)&g_wfragH[fidx];
                uint4 blv = *(const uint4*)&g_wfragL[fidx];
                uint32_t bh[4] = {bhv.x, bhv.y, bhv.z, bhv.w};
                uint32_t bl[4] = {blv.x, blv.y, blv.z, blv.w};
                float* c00 = acc + (0*8 + 2*ntp    )*4;
                float* c10 = acc + (1*8 + 2*ntp    )*4;
                float* c01 = acc + (0*8 + 2*ntp + 1)*4;
                float* c11 = acc + (1*8 + 2*ntp + 1)*4;
                mma16816(c00, aH0, bh);     mma16816(c10, aH1, bh);
                mma16816(c01, aH0, bh + 2); mma16816(c11, aH1, bh + 2);
                mma16816(c00, aL0, bh);     mma16816(c10, aL1, bh);
                mma16816(c01, aL0, bh + 2); mma16816(c11, aL1, bh + 2);
                mma16816(c00, aH0, bl);     mma16816(c10, aH1, bl);
                mma16816(c01, aH0, bl + 2); mma16816(c11, aH1, bl + 2);
            }
        }
    }

    __syncthreads();
    float* ds = (float*)smem;
    {
        int mrow = wid*32 + (lane >> 2);
        int ncol = 2*(lane & 3);
        #pragma unroll
        for (int mt = 0; mt < 2; mt++) {
            int m = mrow + mt*16;
            #pragma unroll
            for (int nt = 0; nt < 8; nt++) {
                int n = nt*8 + ncol;
                const float* c = acc + (mt*8 + nt)*4;
                ds[ n   *260 + m    ] = c[0];
                ds[(n+1)*260 + m    ] = c[1];
                ds[ n   *260 + m + 8] = c[2];
                ds[(n+1)*260 + m + 8] = c[3];
            }
        }
    }
    __syncthreads();
    {
        const float* bs = (const float*)(smem + BIAS_OFF);
        int row_base = oy*WW;
        #pragma unroll
        for (int t = 0; t < 8; t++) {
            int oc = wid*8 + t;
            float bv = bs[oc];
            #pragma unroll
            for (int h = 0; h < 2; h++) {
                int p4 = h*128 + lane*4;
                float4 v = *(const float4*)&ds[oc*260 + p4];
                v.x += bv; v.y += bv; v.z += bv; v.w += bv;
                *(float4*)&out[(b*CC + oc)*HWP + row_base + p4] = v;
            }
        }
    }
}

// ---------------------------------------------------------------------------
extern "C" void kernel_launch(void* const* d_in, const int* in_sizes, int n_in,
                              void* d_out, int out_size)
{
    const float* x      = (const float*)d_in[0];
    const float* conv_w = (const float*)d_in[1];
    const float* conv_b = (const float*)d_in[2];
    const float* off_w  = (const float*)d_in[3];
    const float* off_b  = (const float*)d_in[4];
    const float* dw     = (const float*)d_in[5];
    const float* db     = (const float*)d_in[6];
    float* out = (float*)d_out;

    const int blocks = BB*HH*WW / 256;   // 1024

    wfrag_kernel  <<<72, 256>>>(dw);
    ofrag_kernel  <<<36, 256>>>(off_w);
    conv1_kernel  <<<blocks, 256>>>(x, conv_w, conv_b);

    cudaFuncSetAttribute(offconv_mma_kernel,
                         cudaFuncAttributeMaxDynamicSharedMemorySize, OSMEM_TOT);
    offconv_mma_kernel<<<BB*HH, 256, OSMEM_TOT>>>(off_b);

    cudaFuncSetAttribute(deform_mma_kernel,
                         cudaFuncAttributeMaxDynamicSharedMemorySize, SMEM3_TOT);
    deform_mma_kernel<<<BB*HH, 256, SMEM3_TOT>>>(db, out);
}